// round 2
// baseline (speedup 1.0000x reference)
#include <cuda_runtime.h>
#include <cuda_bf16.h>
#include <math.h>

// Problem dims (fixed by dataset)
#define BB 64
#define SS 512
#define HH 768
#define LL 9

// Scratch (no allocations allowed)
__device__ int g_cnt[BB];            // valid count per batch
__device__ int g_srcl[BB * SS];      // per-batch: src token index for each dest
__device__ int g_items[BB * SS];     // global compacted work list: b<<18 | dest<<9 | src

// ---------------------------------------------------------------------------
// Kernel 1: fill entire output with softmax(bias) (covers all tail slots)
// ---------------------------------------------------------------------------
__global__ __launch_bounds__(256) void fill_kernel(const float* __restrict__ bias,
                                                   float* __restrict__ out) {
    int t = blockIdx.x * blockDim.x + threadIdx.x;
    if (t >= BB * SS) return;
    float v[LL];
#pragma unroll
    for (int l = 0; l < LL; l++) v[l] = __ldg(bias + l);
    float m = v[0];
#pragma unroll
    for (int l = 1; l < LL; l++) m = fmaxf(m, v[l]);
    float s = 0.f;
#pragma unroll
    for (int l = 0; l < LL; l++) { v[l] = __expf(v[l] - m); s += v[l]; }
    float r = 1.f / s;
    float* op = out + (size_t)t * LL;
#pragma unroll
    for (int l = 0; l < LL; l++) op[l] = v[l] * r;
}

// ---------------------------------------------------------------------------
// Kernel 2: per-batch inclusive scan of valid_mask -> src map + counts
// one block (512 threads) per batch row
// ---------------------------------------------------------------------------
__global__ __launch_bounds__(512) void scan_kernel(const int* __restrict__ mask) {
    int b = blockIdx.x;
    int s = threadIdx.x;
    int m = (mask[b * SS + s] == 1) ? 1 : 0;

    __shared__ int wsum[16];
    int lane = s & 31, wid = s >> 5;
    int v = m;
#pragma unroll
    for (int o = 1; o < 32; o <<= 1) {
        int t = __shfl_up_sync(0xffffffffu, v, o);
        if (lane >= o) v += t;
    }
    if (lane == 31) wsum[wid] = v;
    __syncthreads();
    if (wid == 0) {
        int x = (lane < 16) ? wsum[lane] : 0;
#pragma unroll
        for (int o = 1; o < 16; o <<= 1) {
            int t = __shfl_up_sync(0xffffffffu, x, o);
            if (lane >= o) x += t;
        }
        if (lane < 16) wsum[lane] = x;
    }
    __syncthreads();
    int incl = v + (wid ? wsum[wid - 1] : 0);
    if (m) g_srcl[b * SS + (incl - 1)] = s;
    if (s == SS - 1) g_cnt[b] = incl;
}

// ---------------------------------------------------------------------------
// Kernel 3: build globally-compacted work list (perfect load balance)
// ---------------------------------------------------------------------------
__global__ __launch_bounds__(512) void build_kernel() {
    int b = blockIdx.x;
    int d = threadIdx.x;
    __shared__ int scnt[BB];
    __shared__ int soff;
    if (d < BB) scnt[d] = g_cnt[d];
    __syncthreads();
    if (d == 0) {
        int o = 0;
#pragma unroll
        for (int i = 0; i < BB; i++) o += (i < b) ? scnt[i] : 0;
        soff = o;
    }
    __syncthreads();
    if (d < scnt[b]) {
        g_items[soff + d] = (b << 18) | (d << 9) | g_srcl[b * SS + d];
    }
}

// ---------------------------------------------------------------------------
// Kernel 4: main compute. Thread-per-token, warp-uniform h loop so W reads
// from shared memory are pure broadcasts. Double-buffered register staging
// of the token row (8 x float4 per stage) hides DRAM latency at low occupancy.
// ---------------------------------------------------------------------------
#define NBLK 148

__global__ __launch_bounds__(256) void main_kernel(const float* __restrict__ seq,
                                                   const float* __restrict__ W,
                                                   const float* __restrict__ bias,
                                                   float* __restrict__ out) {
    __shared__ float Ws[HH * 12];   // rows padded to 12 floats (float4-aligned)
    __shared__ float Bs[LL];
    __shared__ int s_total;

    int tid = threadIdx.x;
    if (tid == 0) s_total = 0;
    if (tid < LL) Bs[tid] = bias[tid];
    for (int i = tid; i < HH * 12; i += 256) {
        int h = i / 12, c = i % 12;
        Ws[i] = (c < LL) ? W[h * LL + c] : 0.f;
    }
    __syncthreads();
    if (tid < BB) atomicAdd(&s_total, g_cnt[tid]);
    __syncthreads();

    int total = s_total;
    int wid = tid >> 5, lane = tid & 31;
    // spread the work warps: one work warp per SMSP across the chip
    int wp = wid * NBLK + blockIdx.x;
    int item_i = wp * 32 + lane;
    if (item_i >= total) return;

    int item = g_items[item_i];
    int b = item >> 18;
    int d = (item >> 9) & 511;
    int s = item & 511;

    const float4* xp = (const float4*)(seq + (size_t)(b * SS + s) * HH);

    float acc[LL];
#pragma unroll
    for (int l = 0; l < LL; l++) acc[l] = 0.f;

    float4 A[8], Bf[8];

#define CONSUME(BUF, ST)                                                      \
    {                                                                         \
        _Pragma("unroll") for (int k = 0; k < 8; k++) {                       \
            int h = (ST) * 32 + k * 4;                                        \
            float4 xv = BUF[k];                                               \
            float xs_[4] = {xv.x, xv.y, xv.z, xv.w};                          \
            _Pragma("unroll") for (int j = 0; j < 4; j++) {                   \
                const float4* wr = (const float4*)&Ws[(h + j) * 12];          \
                float4 w0 = wr[0];                                            \
                float4 w1 = wr[1];                                            \
                float w8 = Ws[(h + j) * 12 + 8];                              \
                float xs = xs_[j];                                            \
                acc[0] = fmaf(xs, w0.x, acc[0]);                              \
                acc[1] = fmaf(xs, w0.y, acc[1]);                              \
                acc[2] = fmaf(xs, w0.z, acc[2]);                              \
                acc[3] = fmaf(xs, w0.w, acc[3]);                              \
                acc[4] = fmaf(xs, w1.x, acc[4]);                              \
                acc[5] = fmaf(xs, w1.y, acc[5]);                              \
                acc[6] = fmaf(xs, w1.z, acc[6]);                              \
                acc[7] = fmaf(xs, w1.w, acc[7]);                              \
                acc[8] = fmaf(xs, w8, acc[8]);                                \
            }                                                                 \
        }                                                                     \
    }

    // 192 float4 total = 24 stages of 8; process in pairs with double buffer
#pragma unroll
    for (int k = 0; k < 8; k++) A[k] = xp[k];

    for (int st = 0; st < 24; st += 2) {
#pragma unroll
        for (int k = 0; k < 8; k++) Bf[k] = xp[(st + 1) * 8 + k];
        CONSUME(A, st);
        if (st + 2 < 24) {
#pragma unroll
            for (int k = 0; k < 8; k++) A[k] = xp[(st + 2) * 8 + k];
        }
        CONSUME(Bf, (st + 1));
    }
#undef CONSUME

    // bias + softmax
    float v[LL];
#pragma unroll
    for (int l = 0; l < LL; l++) v[l] = acc[l] + Bs[l];
    float m = v[0];
#pragma unroll
    for (int l = 1; l < LL; l++) m = fmaxf(m, v[l]);
    float sum = 0.f;
#pragma unroll
    for (int l = 0; l < LL; l++) { v[l] = __expf(v[l] - m); sum += v[l]; }
    float r = 1.f / sum;

    float* op = out + (size_t)(b * SS + d) * LL;
#pragma unroll
    for (int l = 0; l < LL; l++) op[l] = v[l] * r;
}

// ---------------------------------------------------------------------------
extern "C" void kernel_launch(void* const* d_in, const int* in_sizes, int n_in,
                              void* d_out, int out_size) {
    const float* seq  = (const float*)d_in[0];   // [64,512,768] f32
    const int*   mask = (const int*)d_in[1];     // [64,512] i32
    const float* W    = (const float*)d_in[2];   // [768,9] f32
    const float* bias = (const float*)d_in[3];   // [9] f32
    float* out = (float*)d_out;                  // [64,512,9] f32

    fill_kernel<<<(BB * SS + 255) / 256, 256>>>(bias, out);
    scan_kernel<<<BB, SS>>>(mask);
    build_kernel<<<BB, SS>>>();
    main_kernel<<<NBLK, 256>>>(seq, W, bias, out);
}